// round 9
// baseline (speedup 1.0000x reference)
#include <cuda_runtime.h>
#include <cstdint>

// ---------------- problem constants ----------------
#define IN_DIM   57
#define HDIM     128
#define NCAT     18
#define SEQT     128
#define KX       64            // x-projection K padded 57 -> 64
#define KT       32            // W_hh k-tile streamed from L2
#define NGATE    512           // 4*H
#define MROWS    32            // batch rows per CTA (phase 2)
#define NBLOCKS  128           // 4096 / 32
#define NTHREADS 256
#define MPAD     36            // padded m-stride (16B aligned)

#define W_STAGE  (KT * NGATE)          // 16384 floats per stage
#define XG_ROW   66                    // padded pair-row: 32 m-pairs (64 floats) + 2 pad
#define XG_TILE_FLOATS (256 * XG_ROW)  // 16896 floats = 67584 B per (bblk, t) tile
#define MBAR2_FLOATS 32
#define H2_FLOATS (HDIM * MPAD)        // 4608
#define SMEM2_BYTES ((MBAR2_FLOATS + 2 * W_STAGE + XG_TILE_FLOATS + H2_FLOATS) * 4)

// phase-1
#define P1_THREADS 256
#define P1_AFRAG_BYTES 32768                       // A frags: 2tl x 2wm x 8kc x 32lane x 8w
#define P1_SMEM (P1_AFRAG_BYTES + XG_TILE_FLOATS * 4)   // 32768 + 67584 = 100352

typedef unsigned long long u64;

// ---------------- device globals ----------------
__device__ __align__(128) float    g_whh[HDIM * NGATE];     // [k][n]
__device__ __align__(128) float    g_bias[NGATE];           // b_ih + b_hh
__device__ __align__(128) uint32_t g_wxh[KX * NGATE];       // [k][n] tf32 hi bits
__device__ __align__(128) uint32_t g_wxl[KX * NGATE];       // [k][n] tf32 lo bits
// xg[bblk][t][np 256][XG_ROW]: col-pair (2np,2np+1) x 32 m-rows, padded
__device__ __align__(16) float g_xg[(size_t)NBLOCKS * SEQT * XG_TILE_FLOATS];

// ---------------- helpers ----------------
__device__ __forceinline__ uint32_t smem_u32(const void* p) {
    return (uint32_t)__cvta_generic_to_shared(p);
}
__device__ __forceinline__ u64 dup2(float x) {
    u64 d; asm("mov.b64 %0, {%1, %1};" : "=l"(d) : "f"(x)); return d;
}
__device__ __forceinline__ float2 unpk(u64 v) {
    float2 r; asm("mov.b64 {%0, %1}, %2;" : "=f"(r.x), "=f"(r.y) : "l"(v)); return r;
}
__device__ __forceinline__ void fma2(u64& d, u64 a, u64 b) {
    asm("fma.rn.f32x2 %0, %1, %2, %0;" : "+l"(d) : "l"(a), "l"(b));
}
__device__ __forceinline__ float ex2f(float x) {
    float y; asm("ex2.approx.f32 %0, %1;" : "=f"(y) : "f"(x)); return y;
}
__device__ __forceinline__ float rcpf(float x) {
    float y; asm("rcp.approx.f32 %0, %1;" : "=f"(y) : "f"(x)); return y;
}
__device__ __forceinline__ float sigf(float x) {
    return rcpf(1.0f + ex2f(-1.4426950408889634f * x));
}
__device__ __forceinline__ float tanhf_fast(float x) {
    float e = ex2f(2.8853900817779268f * x);
    return 1.0f - 2.0f * rcpf(e + 1.0f);
}
__device__ __forceinline__ void mbar_init(uint32_t mbar, int cnt) {
    asm volatile("mbarrier.init.shared.b64 [%0], %1;" :: "r"(mbar), "r"(cnt) : "memory");
}
__device__ __forceinline__ void mbar_wait(uint32_t mbar, int phase) {
    asm volatile(
        "{\n\t.reg .pred P;\n\t"
        "LAB_WAIT_%=:\n\t"
        "mbarrier.try_wait.parity.acquire.cta.shared::cta.b64 P, [%0], %1, 0x989680;\n\t"
        "@P bra.uni LAB_DONE_%=;\n\t"
        "bra.uni LAB_WAIT_%=;\n\t"
        "LAB_DONE_%=:\n\t}"
        :: "r"(mbar), "r"(phase) : "memory");
}
__device__ __forceinline__ void bar_arrive(int id, int n) {
    asm volatile("bar.arrive %0, %1;" :: "r"(id), "r"(n) : "memory");
}
__device__ __forceinline__ void bar_sync_named(int id, int n) {
    asm volatile("bar.sync %0, %1;" :: "r"(id), "r"(n) : "memory");
}
__device__ __forceinline__ void issue_bulk(uint32_t dst, const float* src,
                                           uint32_t mbar, int bytes) {
    asm volatile("mbarrier.arrive.expect_tx.shared.b64 _, [%0], %1;"
                 :: "r"(mbar), "r"(bytes) : "memory");
    asm volatile("cp.async.bulk.shared::cluster.global.mbarrier::complete_tx::bytes "
                 "[%0], [%1], %2, [%3];"
                 :: "r"(dst), "l"(src), "r"(bytes), "r"(mbar) : "memory");
}
// tf32 split: hi = rna(v), lo = rna(v - hi)
__device__ __forceinline__ void tf32_split(float v, uint32_t& hb, uint32_t& lb) {
    asm("cvt.rna.tf32.f32 %0, %1;" : "=r"(hb) : "f"(v));
    float hf = __uint_as_float(hb);
    asm("cvt.rna.tf32.f32 %0, %1;" : "=r"(lb) : "f"(v - hf));
}
// m16n8k8 tf32 MMA, D += A*B
__device__ __forceinline__ void mma_tf32(float (&c)[4], const uint4& a,
                                         uint32_t b0, uint32_t b1) {
    asm("mma.sync.aligned.m16n8k8.row.col.f32.tf32.tf32.f32 "
        "{%0,%1,%2,%3}, {%4,%5,%6,%7}, {%8,%9}, {%0,%1,%2,%3};"
        : "+f"(c[0]), "+f"(c[1]), "+f"(c[2]), "+f"(c[3])
        : "r"(a.x), "r"(a.y), "r"(a.z), "r"(a.w), "r"(b0), "r"(b1));
}

// ---------------- prep kernels ----------------
__global__ void prep_whh(const float* __restrict__ W_hh, const float* __restrict__ b_ih,
                         const float* __restrict__ b_hh) {
    int n = threadIdx.x, k = blockIdx.x;          // k 0..127
    g_whh[k * NGATE + n] = W_hh[n * HDIM + k];
    if (k == 0) g_bias[n] = b_ih[n] + b_hh[n];
}
__global__ void prep_wx(const float* __restrict__ W_ih) {
    int n = threadIdx.x, k = blockIdx.x;          // k 0..63
    float w = (k < IN_DIM) ? W_ih[n * IN_DIM + k] : 0.0f;
    uint32_t hb, lb;
    tf32_split(w, hb, lb);
    g_wxh[k * NGATE + n] = hb;
    g_wxl[k * NGATE + n] = lb;
}

// ---------------- phase 1: xg = x @ W_ih^T + bias (mma.sync 3xTF32) ----------------
// CTA = (bblk, t-pair): A rows 0..63 = tloc*32 + b_local; N=512; K=64.
// Warp grid: wm (2 x m16) x wn (4 x n128). Per warp per tloc: 16 n8-tiles (2 groups of 8).
__global__ void __launch_bounds__(P1_THREADS)
xg_kernel(const float* __restrict__ xin) {
    extern __shared__ char sm1[];
    uint32_t* afr   = (uint32_t*)sm1;                      // A fragments (hi/lo)
    float*    out_sh = (float*)(sm1 + P1_AFRAG_BYTES);     // [256 np][XG_ROW]

    const int tid  = threadIdx.x;
    const int lane = tid & 31;
    const int wid  = tid >> 5;
    const int wm   = wid & 1;
    const int wn   = wid >> 1;
    const int gid  = lane >> 2;     // groupID
    const int tig  = lane & 3;      // threadID_in_group
    const int bblk = blockIdx.x >> 6;
    const int t0   = (blockIdx.x & 63) * 2;

    // ---- stage A: 64 rows x 64 k, tf32 hi/lo, pre-swizzled to fragment order ----
    {
        int row = tid & 63;
        int kq  = tid >> 6;                 // 0..3 -> k = kq*16 .. +15
        int tl  = row >> 5;
        int bl  = row & 31;
        int wmm = (bl >> 4) & 1;
        int rin = bl & 15;
        int g   = rin & 7;
        int h8  = rin >> 3;
        const float* xr = xin + ((size_t)(bblk * 32 + bl) * SEQT + (t0 + tl)) * IN_DIM;
#pragma unroll 4
        for (int i = 0; i < 16; ++i) {
            int k = kq * 16 + i;
            float v = (k < IN_DIM) ? xr[k] : 0.0f;
            uint32_t hb, lb;
            tf32_split(v, hb, lb);
            int kc = k >> 3, kin = k & 7;
            int tg = kin & 3, k4 = kin >> 2;
            int reg = h8 + 2 * k4;          // a0..a3 order
            int ln  = g * 4 + tg;
            int base = (((tl * 2 + wmm) * 8 + kc) * 32 + ln) * 8;
            afr[base + reg]     = hb;
            afr[base + 4 + reg] = lb;
        }
    }
    __syncthreads();

    // per-thread W base: row k=tig, col = wn*128 + gid
    const int wbase0 = tig * NGATE + wn * 128 + gid;

    for (int tl = 0; tl < 2; ++tl) {
#pragma unroll 1
        for (int ng = 0; ng < 2; ++ng) {
            float C[8][4];
#pragma unroll
            for (int a = 0; a < 8; ++a)
#pragma unroll
                for (int b = 0; b < 4; ++b) C[a][b] = 0.0f;

#pragma unroll 1
            for (int kc = 0; kc < 8; ++kc) {
                const uint32_t* ap = afr + (((tl * 2 + wm) * 8 + kc) * 32 + lane) * 8;
                uint4 ahv = *(const uint4*)(ap);
                uint4 alv = *(const uint4*)(ap + 4);
                const int kof = kc * 8 * NGATE;
                int a0 = wbase0 + kof + (ng * 8) * 8;
                uint32_t bh0 = g_wxh[a0], bh1 = g_wxh[a0 + 4 * NGATE];
                uint32_t bl0 = g_wxl[a0], bl1 = g_wxl[a0 + 4 * NGATE];
#pragma unroll
                for (int ntl = 0; ntl < 8; ++ntl) {
                    int nn = (ntl + 1) & 7;      // wrap prefetch (last one unused)
                    int a1 = wbase0 + kof + (ng * 8 + nn) * 8;
                    uint32_t nh0 = g_wxh[a1], nh1 = g_wxh[a1 + 4 * NGATE];
                    uint32_t nl0 = g_wxl[a1], nl1 = g_wxl[a1 + 4 * NGATE];
                    mma_tf32(C[ntl], ahv, bh0, bh1);
                    mma_tf32(C[ntl], ahv, bl0, bl1);
                    mma_tf32(C[ntl], alv, bh0, bh1);
                    bh0 = nh0; bh1 = nh1; bl0 = nl0; bl1 = nl1;
                }
            }
            // store C (+bias) into out tile [np][2*row]
#pragma unroll
            for (int ntl = 0; ntl < 8; ++ntl) {
                int np = wn * 64 + (ng * 8 + ntl) * 4 + tig;
                float2 bs = *(const float2*)(g_bias + 2 * np);
                int r0 = wm * 16 + gid;
                *(float2*)(out_sh + np * XG_ROW + 2 * r0) =
                    make_float2(C[ntl][0] + bs.x, C[ntl][1] + bs.y);
                *(float2*)(out_sh + np * XG_ROW + 2 * (r0 + 8)) =
                    make_float2(C[ntl][2] + bs.x, C[ntl][3] + bs.y);
            }
        }
        __syncthreads();
        // coalesced copy out tile -> g_xg
        float* gdst = g_xg + ((size_t)(bblk * SEQT) + t0 + tl) * XG_TILE_FLOATS;
        for (int i = tid; i < XG_TILE_FLOATS / 4; i += P1_THREADS)
            *(uint4*)(gdst + i * 4) = *(const uint4*)(out_sh + i * 4);
        __syncthreads();
    }
}

// ---------------- phase 2: recurrence (K=128 only) ----------------
__device__ __forceinline__ void gemm_tile(const float* __restrict__ ab,
                                          const float* __restrict__ wb,
                                          u64 (&acc)[4][8]) {
#pragma unroll 8
    for (int kk = 0; kk < KT; ++kk) {
        float4 a0 = *(const float4*)(ab + kk * MPAD);
        float4 a1 = *(const float4*)(ab + kk * MPAD + 4);
        u64 ad[8];
        ad[0] = dup2(a0.x); ad[1] = dup2(a0.y); ad[2] = dup2(a0.z); ad[3] = dup2(a0.w);
        ad[4] = dup2(a1.x); ad[5] = dup2(a1.y); ad[6] = dup2(a1.z); ad[7] = dup2(a1.w);
        const float* wr = wb + kk * NGATE;
        u64 wv[4];
        wv[0] = *(const u64*)(wr);
        wv[1] = *(const u64*)(wr + 128);
        wv[2] = *(const u64*)(wr + 256);
        wv[3] = *(const u64*)(wr + 384);
#pragma unroll
        for (int gg = 0; gg < 4; ++gg)
#pragma unroll
            for (int mi = 0; mi < 8; ++mi)
                fma2(acc[gg][mi], ad[mi], wv[gg]);
    }
}

__global__ void __launch_bounds__(NTHREADS, 1)
lstm_kernel(const float* __restrict__ W_out, const float* __restrict__ b_out,
            float* __restrict__ out) {
    extern __shared__ float smem[];
    u64*   mbar  = (u64*)smem;                    // [0]=w0 [1]=w1 [2]=xg
    float* w_sh  = smem + MBAR2_FLOATS;           // [2][KT][512]
    float* xg_sh = w_sh + 2 * W_STAGE;            // [256 np][XG_ROW]
    float* h_sh  = xg_sh + XG_TILE_FLOATS;        // [HDIM][MPAD] single buffer

    const int tid = threadIdx.x;
    const int wid = tid >> 5;
    const int hg  = tid & 63;
    const int mg  = tid >> 6;
    const int m0  = blockIdx.x * MROWS;

    const uint32_t mb0  = smem_u32(mbar);
    const uint32_t mb1  = mb0 + 8;
    const uint32_t xgmb = mb0 + 16;
    const uint32_t w0a  = smem_u32(w_sh);
    const uint32_t w1a  = w0a + W_STAGE * 4;
    const uint32_t xga  = smem_u32(xg_sh);

    if (tid == 0) {
        mbar_init(mb0, 1); mbar_init(mb1, 1); mbar_init(xgmb, 1);
    }
    for (int i = tid; i < H2_FLOATS; i += NTHREADS) h_sh[i] = 0.0f;
    __syncthreads();

    if (tid == 0) {
        issue_bulk(w0a, g_whh,           mb0, W_STAGE * 4);    // tile 0
        issue_bulk(w1a, g_whh + W_STAGE, mb1, W_STAGE * 4);    // tile 1
        issue_bulk(xga, g_xg + (size_t)blockIdx.x * SEQT * XG_TILE_FLOATS,
                   xgmb, XG_TILE_FLOATS * 4);                  // xg(0)
    }

    float c0[8], c1[8];
#pragma unroll
    for (int i = 0; i < 8; ++i) { c0[i] = 0.0f; c1[i] = 0.0f; }

    u64 acc[4][8];
    const float* ws0 = w_sh + hg * 2;
    const float* ws1 = w_sh + W_STAGE + hg * 2;
    const float* hb  = h_sh + mg * 8;

    int ph0 = 0, ph1 = 0, phx = 0;

#define RELEASE(barid, doissue, dsta, srcp, mbx, nbytes)                        \
    {                                                                           \
        if (wid == 0) {                                                         \
            bar_sync_named(barid, NTHREADS);                                    \
            if (tid == 0 && (doissue)) issue_bulk(dsta, srcp, mbx, nbytes);     \
        } else {                                                                \
            bar_arrive(barid, NTHREADS);                                        \
        }                                                                       \
    }

    for (int t = 0; t < SEQT; ++t) {
        const bool more = (t + 1 < SEQT);

        // ---------- acc init from xg tile (bias already folded in) ----------
        mbar_wait(xgmb, phx); phx ^= 1;
#pragma unroll
        for (int gg = 0; gg < 4; ++gg) {
            const float* base = xg_sh + (gg * 64 + hg) * XG_ROW + mg * 16;
#pragma unroll
            for (int mi = 0; mi < 8; ++mi)
                acc[gg][mi] = *(const u64*)(base + mi * 2);
        }
        RELEASE(3, more, xga,
                g_xg + ((size_t)blockIdx.x * SEQT + t + 1) * XG_TILE_FLOATS,
                xgmb, XG_TILE_FLOATS * 4);

        // ---------- 4 W_hh tiles ----------
        mbar_wait(mb0, ph0); ph0 ^= 1;
        gemm_tile(hb, ws0, acc);
        RELEASE(1, true, w0a, g_whh + 2 * W_STAGE, mb0, W_STAGE * 4);

        mbar_wait(mb1, ph1); ph1 ^= 1;
        gemm_tile(hb + KT * MPAD, ws1, acc);
        RELEASE(2, true, w1a, g_whh + 3 * W_STAGE, mb1, W_STAGE * 4);

        mbar_wait(mb0, ph0); ph0 ^= 1;
        gemm_tile(hb + 2 * KT * MPAD, ws0, acc);
        RELEASE(1, more, w0a, g_whh, mb0, W_STAGE * 4);

        mbar_wait(mb1, ph1); ph1 ^= 1;
        gemm_tile(hb + 3 * KT * MPAD, ws1, acc);
        RELEASE(2, more, w1a, g_whh + W_STAGE, mb1, W_STAGE * 4);

        __syncthreads();   // all h(t) reads done before overwrite

        // ---------- epilogue ----------
        float* hout = h_sh + mg * 8;
#pragma unroll
        for (int mi = 0; mi < 8; ++mi) {
            float2 iv = unpk(acc[0][mi]);
            float2 fv = unpk(acc[1][mi]);
            float2 gv = unpk(acc[2][mi]);
            float2 ov = unpk(acc[3][mi]);
            float i0 = sigf(iv.x), f0 = sigf(fv.x), g0 = tanhf_fast(gv.x), o0 = sigf(ov.x);
            c0[mi] = f0 * c0[mi] + i0 * g0;
            hout[(hg * 2    ) * MPAD + mi] = o0 * tanhf_fast(c0[mi]);
            float i1 = sigf(iv.y), f1 = sigf(fv.y), g1 = tanhf_fast(gv.y), o1 = sigf(ov.y);
            c1[mi] = f1 * c1[mi] + i1 * g1;
            hout[(hg * 2 + 1) * MPAD + mi] = o1 * tanhf_fast(c1[mi]);
        }
        __syncthreads();   // h(t+1) published
    }
#undef RELEASE

    // ---------- final Linear ----------
    for (int idx = tid; idx < MROWS * NCAT; idx += NTHREADS) {
        int mm  = idx / NCAT;
        int cat = idx - mm * NCAT;
        float sacc = b_out[cat];
        const float* wr = W_out + cat * HDIM;
#pragma unroll 8
        for (int k = 0; k < HDIM; ++k)
            sacc += h_sh[k * MPAD + mm] * wr[k];
        out[(size_t)(m0 + mm) * NCAT + cat] = sacc;
    }
}

// ---------------- launch ----------------
extern "C" void kernel_launch(void* const* d_in, const int* in_sizes, int n_in,
                              void* d_out, int out_size) {
    const float* x     = (const float*)d_in[0];
    const float* W_ih  = (const float*)d_in[1];
    const float* W_hh  = (const float*)d_in[2];
    const float* b_ih  = (const float*)d_in[3];
    const float* b_hh  = (const float*)d_in[4];
    const float* W_out = (const float*)d_in[5];
    const float* b_out = (const float*)d_in[6];
    float* out = (float*)d_out;

    cudaFuncSetAttribute(xg_kernel,   cudaFuncAttributeMaxDynamicSharedMemorySize, P1_SMEM);
    cudaFuncSetAttribute(lstm_kernel, cudaFuncAttributeMaxDynamicSharedMemorySize, SMEM2_BYTES);

    prep_whh<<<HDIM, NGATE>>>(W_hh, b_ih, b_hh);
    prep_wx<<<KX, NGATE>>>(W_ih);
    xg_kernel<<<NBLOCKS * 64, P1_THREADS, P1_SMEM>>>(x);
    lstm_kernel<<<NBLOCKS, NTHREADS, SMEM2_BYTES>>>(W_out, b_out, out);
}